// round 6
// baseline (speedup 1.0000x reference)
#include <cuda_runtime.h>
#include <cuda_fp16.h>
#include <cuda_bf16.h>

#define N_NODES 600000
#define N_EDGES 2400000
#define LEADS 12
#define NUM_GRAPHS 50000
#define F_IN 128
#define HDIM 64
#define OUT_DIM 32

#define SCAN_NB 586   // ceil(600000/1024)

// ---------------- packed fp32x2 FMA -------------------------------------------
__device__ __forceinline__ void fma2(unsigned long long& d,
                                     unsigned long long a,
                                     unsigned long long b) {
    asm("fma.rn.f32x2 %0, %1, %2, %0;" : "+l"(d) : "l"(a), "l"(b));
}
__device__ __forceinline__ float hsum2(unsigned long long d) {
    float lo = __uint_as_float((unsigned int)(d & 0xffffffffULL));
    float hi = __uint_as_float((unsigned int)(d >> 32));
    return lo + hi;
}

// ---------------- scratch (device globals) ------------------------------------
__device__ __half g_hH[(size_t)N_NODES * HDIM];   // fp16 GEMM output (gather source)
__device__ float  g_agg[(size_t)N_NODES * HDIM];  // fp32 aggregated layer output
__device__ float  g_dinv[N_NODES];
__device__ int    g_deg[N_NODES];
__device__ int    g_rowoff[N_NODES + 1];
__device__ int    g_cursor[N_NODES];
__device__ int    g_csr[N_EDGES];
__device__ int    g_bsum[SCAN_NB];
__device__ int    g_boff[SCAN_NB];

// ---------------- degree / CSR build -------------------------------------------
__global__ void k_deg_zero() {
    int i = blockIdx.x * blockDim.x + threadIdx.x;
    if (i < N_NODES) g_deg[i] = 0;
}

__global__ void k_deg_count(const int* __restrict__ dst) {
    int e = blockIdx.x * blockDim.x + threadIdx.x;
    if (e < N_EDGES) atomicAdd(&g_deg[dst[e]], 1);
}

__global__ void k_dinv() {
    int i = blockIdx.x * blockDim.x + threadIdx.x;
    if (i < N_NODES) g_dinv[i] = rsqrtf((float)(g_deg[i] + 1));
}

__global__ void k_scan1() {
    __shared__ int sh[1024];
    int i = blockIdx.x * 1024 + threadIdx.x;
    int v = (i < N_NODES) ? g_deg[i] : 0;
    sh[threadIdx.x] = v;
    __syncthreads();
    #pragma unroll
    for (int off = 1; off < 1024; off <<= 1) {
        int t = 0;
        if (threadIdx.x >= off) t = sh[threadIdx.x - off];
        __syncthreads();
        if (threadIdx.x >= off) sh[threadIdx.x] += t;
        __syncthreads();
    }
    if (i < N_NODES) g_rowoff[i] = sh[threadIdx.x] - v;   // exclusive
    if (threadIdx.x == 1023) g_bsum[blockIdx.x] = sh[1023];
}

__global__ void k_scan2() {
    __shared__ int sh[1024];
    int v = (threadIdx.x < SCAN_NB) ? g_bsum[threadIdx.x] : 0;
    sh[threadIdx.x] = v;
    __syncthreads();
    #pragma unroll
    for (int off = 1; off < 1024; off <<= 1) {
        int t = 0;
        if (threadIdx.x >= off) t = sh[threadIdx.x - off];
        __syncthreads();
        if (threadIdx.x >= off) sh[threadIdx.x] += t;
        __syncthreads();
    }
    if (threadIdx.x < SCAN_NB) g_boff[threadIdx.x] = sh[threadIdx.x] - v;
}

__global__ void k_scan3() {
    int i = blockIdx.x * blockDim.x + threadIdx.x;
    if (i < N_NODES) {
        int ro = g_rowoff[i] + g_boff[i >> 10];
        g_rowoff[i] = ro;
        g_cursor[i] = ro;
    }
    if (i == 0) g_rowoff[N_NODES] = N_EDGES;
}

__global__ void k_place(const int* __restrict__ src, const int* __restrict__ dst) {
    int e = blockIdx.x * blockDim.x + threadIdx.x;
    if (e < N_EDGES) {
        int pos = atomicAdd(&g_cursor[dst[e]], 1);
        g_csr[pos] = src[e];
    }
}

// ---------------- GEMM: C_fp16[N,64] = (act(A)[N,K] @ W[K,64]) * dinv[row] -----
// BM rows/block, 256 threads, thread tile (BM/16) rows x 4 cols, fp32x2 FMA.
template<int K, int BM, bool ACT>
__global__ void k_gemm(const float* __restrict__ A, const float* __restrict__ W,
                       const float* __restrict__ bias, __half* __restrict__ C) {
    constexpr int KQ = K / 4;
    constexpr int KP = K + 4;
    constexpr int TM = BM / 16;
    extern __shared__ float smem[];
    float* sA  = smem;            // [BM][K]
    float* sWt = smem + BM * K;   // [64][K+4]

    const int tid = threadIdx.x;
    const int r0 = blockIdx.x * BM;

    for (int i = tid; i < K * 64; i += 256) {
        int k = i >> 6, c = i & 63;
        sWt[c * KP + k] = W[i];
    }
    const float4* A4 = (const float4*)A;
    const float4* B4 = (const float4*)bias;
    float4* sA4 = (float4*)sA;
    for (int i = tid; i < BM * KQ; i += 256) {
        int row = i / KQ, kq = i - row * KQ;
        float4 a = make_float4(0.f, 0.f, 0.f, 0.f);
        if (r0 + row < N_NODES) a = A4[(size_t)(r0 + row) * KQ + kq];
        if (ACT) {
            float4 b = B4[kq];
            a.x = fmaxf(a.x + b.x, 0.f);
            a.y = fmaxf(a.y + b.y, 0.f);
            a.z = fmaxf(a.z + b.z, 0.f);
            a.w = fmaxf(a.w + b.w, 0.f);
        }
        sA4[i] = a;
    }
    __syncthreads();

    const int ci = tid & 15;
    const int ri = tid >> 4;
    unsigned long long acc[TM][4];
    #pragma unroll
    for (int j = 0; j < TM; j++)
        #pragma unroll
        for (int c = 0; c < 4; c++) acc[j][c] = 0ULL;

    const float* wbase = sWt + ci * 4 * KP;
    const float* abase = sA + ri * TM * K;

    #pragma unroll 4
    for (int k4 = 0; k4 < KQ; k4++) {
        ulonglong2 w0 = *(const ulonglong2*)(wbase + 0 * KP + k4 * 4);
        ulonglong2 w1 = *(const ulonglong2*)(wbase + 1 * KP + k4 * 4);
        ulonglong2 w2 = *(const ulonglong2*)(wbase + 2 * KP + k4 * 4);
        ulonglong2 w3 = *(const ulonglong2*)(wbase + 3 * KP + k4 * 4);
        #pragma unroll
        for (int j = 0; j < TM; j++) {
            ulonglong2 a = *(const ulonglong2*)(abase + j * K + k4 * 4);
            fma2(acc[j][0], a.x, w0.x); fma2(acc[j][0], a.y, w0.y);
            fma2(acc[j][1], a.x, w1.x); fma2(acc[j][1], a.y, w1.y);
            fma2(acc[j][2], a.x, w2.x); fma2(acc[j][2], a.y, w2.y);
            fma2(acc[j][3], a.x, w3.x); fma2(acc[j][3], a.y, w3.y);
        }
    }

    __half2* C2 = (__half2*)C;
    #pragma unroll
    for (int j = 0; j < TM; j++) {
        int r = r0 + ri * TM + j;
        if (r < N_NODES) {
            float dv = g_dinv[r];
            C2[(size_t)r * 32 + ci * 2]     = __floats2half2_rn(hsum2(acc[j][0]) * dv,
                                                                hsum2(acc[j][1]) * dv);
            C2[(size_t)r * 32 + ci * 2 + 1] = __floats2half2_rn(hsum2(acc[j][2]) * dv,
                                                                hsum2(acc[j][3]) * dv);
        }
    }
}

// ---------------- CSR aggregation (fp16 gather, fp32 accumulate) ---------------
// 8 threads per node; thread owns 8 consecutive features (uint4 = 16B).
// Edge loop unrolled x2 with independent accumulators for MLP.
__device__ __forceinline__ void acc_row(float* a, uint4 r) {
    const __half2* p = (const __half2*)&r;
    #pragma unroll
    for (int i = 0; i < 4; i++) {
        float2 f = __half22float2(p[i]);
        a[2 * i] += f.x; a[2 * i + 1] += f.y;
    }
}

__global__ void k_aggregate() {
    int idx = blockIdx.x * blockDim.x + threadIdx.x;   // over N*8
    if (idx >= N_NODES * 8) return;
    int node = idx >> 3;
    int q = idx & 7;
    const uint4* h4 = (const uint4*)g_hH;

    float a[8], b[8];
    #pragma unroll
    for (int i = 0; i < 8; i++) { a[i] = 0.f; b[i] = 0.f; }
    acc_row(a, h4[(size_t)node * 8 + q]);   // self

    int e = g_rowoff[node], e1 = g_rowoff[node + 1];
    for (; e + 2 <= e1; e += 2) {
        int s0 = __ldg(&g_csr[e]);
        int s1 = __ldg(&g_csr[e + 1]);
        uint4 r0 = h4[(size_t)s0 * 8 + q];
        uint4 r1 = h4[(size_t)s1 * 8 + q];
        acc_row(a, r0);
        acc_row(b, r1);
    }
    if (e < e1) {
        int s0 = __ldg(&g_csr[e]);
        acc_row(a, h4[(size_t)s0 * 8 + q]);
    }

    float dv = g_dinv[node];
    #pragma unroll
    for (int i = 0; i < 8; i++) a[i] = (a[i] + b[i]) * dv;
    float4* agg4 = (float4*)g_agg;
    agg4[(size_t)node * 16 + q * 2]     = make_float4(a[0], a[1], a[2], a[3]);
    agg4[(size_t)node * 16 + q * 2 + 1] = make_float4(a[4], a[5], a[6], a[7]);
}

// ---------------- attention + pooling + final linear ---------------------------
// 1 warp per graph, 8 warps per block. Applies relu(h + b3) on load of g_agg.
__global__ void k_attn(const float* __restrict__ Wa, const float* __restrict__ v,
                       const float* __restrict__ Wl, const float* __restrict__ bl,
                       const float* __restrict__ b3,
                       float* __restrict__ out, float* __restrict__ lw) {
    __shared__ float sWaT[64 * 68];
    __shared__ float sWl[128 * 32];
    __shared__ float sV[64];
    __shared__ float sBl[32];
    __shared__ float sB3[64];
    __shared__ float sH[8][LEADS * 64];
    __shared__ float sScore[8][LEADS];
    __shared__ float sPool[8][128];

    int tid = threadIdx.x;
    for (int i = tid; i < 4096; i += 256) {
        int k = i >> 6, c = i & 63;
        sWaT[c * 68 + k] = Wa[i];
        sWl[i] = Wl[i];
    }
    if (tid < 64) { sV[tid] = v[tid]; sB3[tid] = b3[tid]; }
    if (tid < 32) sBl[tid] = bl[tid];
    __syncthreads();

    int w = tid >> 5, lane = tid & 31;
    int g = blockIdx.x * 8 + w;
    if (g >= NUM_GRAPHS) return;

    float* hs = sH[w];
    const float4* hg4 = (const float4*)(g_agg + (size_t)g * (LEADS * 64));
    const float4* b34 = (const float4*)sB3;
    float4* hs4 = (float4*)hs;
    #pragma unroll
    for (int j = 0; j < 6; j++) {
        int id = lane + 32 * j;
        float4 hv = hg4[id];
        float4 b = b34[id & 15];
        hv.x = fmaxf(hv.x + b.x, 0.f);
        hv.y = fmaxf(hv.y + b.y, 0.f);
        hv.z = fmaxf(hv.z + b.z, 0.f);
        hv.w = fmaxf(hv.w + b.w, 0.f);
        hs4[id] = hv;
    }
    __syncwarp();

    unsigned long long e0a[LEADS], e1a[LEADS];
    #pragma unroll
    for (int l = 0; l < LEADS; l++) { e0a[l] = 0ULL; e1a[l] = 0ULL; }
    const float* w0base = sWaT + lane * 68;
    const float* w1base = sWaT + (lane + 32) * 68;
    #pragma unroll 4
    for (int k4 = 0; k4 < 16; k4++) {
        ulonglong2 w0 = *(const ulonglong2*)(w0base + k4 * 4);
        ulonglong2 w1 = *(const ulonglong2*)(w1base + k4 * 4);
        #pragma unroll
        for (int l = 0; l < LEADS; l++) {
            ulonglong2 a = *(const ulonglong2*)(hs + l * 64 + k4 * 4);
            fma2(e0a[l], a.x, w0.x); fma2(e0a[l], a.y, w0.y);
            fma2(e1a[l], a.x, w1.x); fma2(e1a[l], a.y, w1.y);
        }
    }
    float v0 = sV[lane], v1 = sV[lane + 32];
    #pragma unroll
    for (int l = 0; l < LEADS; l++) {
        float s = tanhf(hsum2(e0a[l])) * v0 + tanhf(hsum2(e1a[l])) * v1;
        #pragma unroll
        for (int o = 16; o > 0; o >>= 1) s += __shfl_xor_sync(0xffffffff, s, o);
        if (lane == 0) sScore[w][l] = s;
    }
    __syncwarp();

    float sc[LEADS];
    #pragma unroll
    for (int l = 0; l < LEADS; l++) sc[l] = sScore[w][l];
    float m = sc[0];
    #pragma unroll
    for (int l = 1; l < LEADS; l++) m = fmaxf(m, sc[l]);
    float sum = 0.f;
    #pragma unroll
    for (int l = 0; l < LEADS; l++) { sc[l] = expf(sc[l] - m); sum += sc[l]; }
    float inv = 1.f / sum;
    #pragma unroll
    for (int l = 0; l < LEADS; l++) sc[l] *= inv;
    if (lane < LEADS) lw[(size_t)g * LEADS + lane] = sc[lane];

    #pragma unroll
    for (int half = 0; half < 2; half++) {
        int f = lane + 32 * half;
        float mx = -1e30f, sm = 0.f;
        #pragma unroll
        for (int l = 0; l < LEADS; l++) {
            float val = hs[l * 64 + f] * sc[l];
            mx = fmaxf(mx, val);
            sm += val;
        }
        sPool[w][f] = mx;
        sPool[w][64 + f] = sm * (1.f / 12.f);
    }
    __syncwarp();

    float acc = sBl[lane];
    #pragma unroll 16
    for (int f = 0; f < 128; f++) acc += sPool[w][f] * sWl[f * 32 + lane];
    out[(size_t)g * 32 + lane] = fmaxf(acc, 0.f);
}

// ---------------- launch --------------------------------------------------------
extern "C" void kernel_launch(void* const* d_in, const int* in_sizes, int n_in,
                              void* d_out, int out_size) {
    const float* x    = (const float*)d_in[0];
    const int*   ei   = (const int*)d_in[1];
    const int*   srcp = ei;
    const int*   dstp = ei + N_EDGES;
    const float* W1 = (const float*)d_in[3];
    const float* b1 = (const float*)d_in[4];
    const float* W2 = (const float*)d_in[5];
    const float* b2 = (const float*)d_in[6];
    const float* W3 = (const float*)d_in[7];
    const float* b3 = (const float*)d_in[8];
    const float* Wa = (const float*)d_in[9];
    const float* vv = (const float*)d_in[10];
    const float* Wl = (const float*)d_in[11];
    const float* bl = (const float*)d_in[12];

    float* out = (float*)d_out;                                  // [G,32]
    float* lw  = (float*)d_out + (size_t)NUM_GRAPHS * OUT_DIM;   // [G,12]

    __half* hp;  cudaGetSymbolAddress((void**)&hp,  g_hH);
    float* aggp; cudaGetSymbolAddress((void**)&aggp, g_agg);

    const int SM1 = 64 * 128 * 4 + 64 * 132 * 4;    // BM=64, K=128: 66560 B
    const int SM2 = 128 * 64 * 4 + 64 * 68 * 4;     // BM=128, K=64: 50176 B
    cudaFuncSetAttribute(k_gemm<128, 64, false>, cudaFuncAttributeMaxDynamicSharedMemorySize, SM1);
    cudaFuncSetAttribute(k_gemm<64, 128, true>,  cudaFuncAttributeMaxDynamicSharedMemorySize, SM2);

    const int T = 256;
    const int gN = (N_NODES + T - 1) / T;
    const int gE = (N_EDGES + T - 1) / T;

    // launches 1-3
    k_deg_zero<<<gN, T>>>();
    k_deg_count<<<gE, T>>>(dstp);
    k_dinv<<<gN, T>>>();

    // launch 4 (ncu-profiled slot): heavy layer-1 GEMM
    k_gemm<128, 64, false><<<(N_NODES + 63) / 64, 256, SM1>>>(x, W1, nullptr, hp);

    // CSR build
    k_scan1<<<SCAN_NB, 1024>>>();
    k_scan2<<<1, 1024>>>();
    k_scan3<<<(N_NODES + 1023) / 1024, 1024>>>();
    k_place<<<gE, T>>>(srcp, dstp);

    const int GEMM_GRID = (N_NODES + 127) / 128;
    const int AGG_GRID  = (N_NODES * 8 + T - 1) / T;

    k_aggregate<<<AGG_GRID, T>>>();
    k_gemm<64, 128, true><<<GEMM_GRID, 256, SM2>>>(aggp, W2, b1, hp);
    k_aggregate<<<AGG_GRID, T>>>();
    k_gemm<64, 128, true><<<GEMM_GRID, 256, SM2>>>(aggp, W3, b2, hp);
    k_aggregate<<<AGG_GRID, T>>>();

    k_attn<<<(NUM_GRAPHS + 7) / 8, 256>>>(Wa, vv, Wl, bl, b3, out, lw);
}

// round 7
// speedup vs baseline: 1.6051x; 1.6051x over previous
#include <cuda_runtime.h>
#include <cuda_fp16.h>
#include <cuda_bf16.h>

#define N_NODES 600000
#define N_EDGES 2400000
#define LEADS 12
#define NUM_GRAPHS 50000
#define F_IN 128
#define HDIM 64
#define OUT_DIM 32

#define SCAN_NB 586   // ceil(600000/1024)

// ---------------- packed fp32x2 FMA (used in attention) ------------------------
__device__ __forceinline__ void fma2(unsigned long long& d,
                                     unsigned long long a,
                                     unsigned long long b) {
    asm("fma.rn.f32x2 %0, %1, %2, %0;" : "+l"(d) : "l"(a), "l"(b));
}
__device__ __forceinline__ float hsum2(unsigned long long d) {
    float lo = __uint_as_float((unsigned int)(d & 0xffffffffULL));
    float hi = __uint_as_float((unsigned int)(d >> 32));
    return lo + hi;
}

// ---------------- bf16 mma m16n8k16, fp32 accumulate ---------------------------
__device__ __forceinline__ void mma_bf16(float* c, const unsigned* a,
                                         unsigned b0, unsigned b1) {
    asm volatile(
        "mma.sync.aligned.m16n8k16.row.col.f32.bf16.bf16.f32 "
        "{%0,%1,%2,%3}, {%4,%5,%6,%7}, {%8,%9}, {%0,%1,%2,%3};"
        : "+f"(c[0]), "+f"(c[1]), "+f"(c[2]), "+f"(c[3])
        : "r"(a[0]), "r"(a[1]), "r"(a[2]), "r"(a[3]), "r"(b0), "r"(b1));
}

// ---------------- scratch (device globals) ------------------------------------
__device__ __half g_hH[(size_t)N_NODES * HDIM];   // fp16 GEMM output (gather source)
__device__ float  g_agg[(size_t)N_NODES * HDIM];  // fp32 aggregated layer output
__device__ float  g_dinv[N_NODES];
__device__ int    g_deg[N_NODES];
__device__ int    g_rowoff[N_NODES + 1];
__device__ int    g_cursor[N_NODES];
__device__ int    g_csr[N_EDGES];
__device__ int    g_bsum[SCAN_NB];
__device__ int    g_boff[SCAN_NB];

// ---------------- degree / CSR build -------------------------------------------
__global__ void k_deg_zero() {
    int i = blockIdx.x * blockDim.x + threadIdx.x;
    if (i < N_NODES) g_deg[i] = 0;
}

__global__ void k_deg_count(const int* __restrict__ dst) {
    int e = blockIdx.x * blockDim.x + threadIdx.x;
    if (e < N_EDGES) atomicAdd(&g_deg[dst[e]], 1);
}

__global__ void k_dinv() {
    int i = blockIdx.x * blockDim.x + threadIdx.x;
    if (i < N_NODES) g_dinv[i] = rsqrtf((float)(g_deg[i] + 1));
}

__global__ void k_scan1() {
    __shared__ int sh[1024];
    int i = blockIdx.x * 1024 + threadIdx.x;
    int v = (i < N_NODES) ? g_deg[i] : 0;
    sh[threadIdx.x] = v;
    __syncthreads();
    #pragma unroll
    for (int off = 1; off < 1024; off <<= 1) {
        int t = 0;
        if (threadIdx.x >= off) t = sh[threadIdx.x - off];
        __syncthreads();
        if (threadIdx.x >= off) sh[threadIdx.x] += t;
        __syncthreads();
    }
    if (i < N_NODES) g_rowoff[i] = sh[threadIdx.x] - v;   // exclusive
    if (threadIdx.x == 1023) g_bsum[blockIdx.x] = sh[1023];
}

__global__ void k_scan2() {
    __shared__ int sh[1024];
    int v = (threadIdx.x < SCAN_NB) ? g_bsum[threadIdx.x] : 0;
    sh[threadIdx.x] = v;
    __syncthreads();
    #pragma unroll
    for (int off = 1; off < 1024; off <<= 1) {
        int t = 0;
        if (threadIdx.x >= off) t = sh[threadIdx.x - off];
        __syncthreads();
        if (threadIdx.x >= off) sh[threadIdx.x] += t;
        __syncthreads();
    }
    if (threadIdx.x < SCAN_NB) g_boff[threadIdx.x] = sh[threadIdx.x] - v;
}

__global__ void k_scan3() {
    int i = blockIdx.x * blockDim.x + threadIdx.x;
    if (i < N_NODES) {
        int ro = g_rowoff[i] + g_boff[i >> 10];
        g_rowoff[i] = ro;
        g_cursor[i] = ro;
    }
    if (i == 0) g_rowoff[N_NODES] = N_EDGES;
}

__global__ void k_place(const int* __restrict__ src, const int* __restrict__ dst) {
    int e = blockIdx.x * blockDim.x + threadIdx.x;
    if (e < N_EDGES) {
        int pos = atomicAdd(&g_cursor[dst[e]], 1);
        g_csr[pos] = src[e];
    }
}

// ---------------- tensor-core GEMM: C_fp16 = (act(A) @ W) * dinv[row] ----------
// bf16 split (hi+lo), 3 HMMA products, fp32 accumulate. 128 threads, BM=128.
// Warp owns 32 rows (2 m-tiles) x 64 cols (8 n-tiles).
template<int K, bool ACT>
__global__ void k_gemm_mma(const float* __restrict__ A, const float* __restrict__ W,
                           const float* __restrict__ bias, __half* __restrict__ C) {
    constexpr int BM = 128;
    constexpr int KP = K + 8;    // padded row (bank-conflict-free fragment loads)
    constexpr int KQ = K / 4;
    extern __shared__ char smem_raw[];
    __nv_bfloat16* sAhi = (__nv_bfloat16*)smem_raw;            // [BM][KP]
    __nv_bfloat16* sAlo = sAhi + BM * KP;                      // [BM][KP]
    __nv_bfloat16* sWhi = sAlo + BM * KP;                      // [64][KP] (transposed)
    __nv_bfloat16* sWlo = sWhi + 64 * KP;                      // [64][KP]

    const int tid = threadIdx.x;
    const int r0 = blockIdx.x * BM;

    // stage W transposed, split hi/lo
    for (int i = tid; i < K * 64; i += 128) {
        int k = i >> 6, c = i & 63;
        float w = W[i];
        __nv_bfloat16 hi = __float2bfloat16_rn(w);
        sWhi[c * KP + k] = hi;
        sWlo[c * KP + k] = __float2bfloat16_rn(w - __bfloat162float(hi));
    }
    // stage A split hi/lo (+ optional fused bias+relu)
    const float4* A4 = (const float4*)A;
    const float4* B4 = (const float4*)bias;
    for (int i = tid; i < BM * KQ; i += 128) {
        int row = i / KQ, kq = i - row * KQ;
        float4 a = make_float4(0.f, 0.f, 0.f, 0.f);
        if (r0 + row < N_NODES) a = A4[(size_t)(r0 + row) * KQ + kq];
        if (ACT) {
            float4 b = B4[kq];
            a.x = fmaxf(a.x + b.x, 0.f);
            a.y = fmaxf(a.y + b.y, 0.f);
            a.z = fmaxf(a.z + b.z, 0.f);
            a.w = fmaxf(a.w + b.w, 0.f);
        }
        float av[4] = {a.x, a.y, a.z, a.w};
        __nv_bfloat16 hv[4], lv[4];
        #pragma unroll
        for (int j = 0; j < 4; j++) {
            hv[j] = __float2bfloat16_rn(av[j]);
            lv[j] = __float2bfloat16_rn(av[j] - __bfloat162float(hv[j]));
        }
        __nv_bfloat162* ph = (__nv_bfloat162*)(sAhi + row * KP + kq * 4);
        __nv_bfloat162* pl = (__nv_bfloat162*)(sAlo + row * KP + kq * 4);
        ph[0] = __nv_bfloat162(hv[0], hv[1]);
        ph[1] = __nv_bfloat162(hv[2], hv[3]);
        pl[0] = __nv_bfloat162(lv[0], lv[1]);
        pl[1] = __nv_bfloat162(lv[2], lv[3]);
    }
    __syncthreads();

    const int warp = tid >> 5;
    const int lane = tid & 31;
    const int g  = lane >> 2;       // fragment group row / B col
    const int t2 = (lane & 3) * 2;  // fragment k-pair base
    const int wrow = warp * 32;     // warp's first row in block

    float acc[2][8][4];
    #pragma unroll
    for (int mt = 0; mt < 2; mt++)
        #pragma unroll
        for (int n = 0; n < 8; n++)
            #pragma unroll
            for (int c = 0; c < 4; c++) acc[mt][n][c] = 0.f;

    #pragma unroll
    for (int kb = 0; kb < K / 16; kb++) {
        const int kO = kb * 16 + t2;
        unsigned ahi[2][4], alo[2][4];
        #pragma unroll
        for (int mt = 0; mt < 2; mt++) {
            int rA = wrow + mt * 16 + g;
            const unsigned* pH0 = (const unsigned*)(sAhi + rA * KP + kO);
            const unsigned* pH8 = (const unsigned*)(sAhi + (rA + 8) * KP + kO);
            const unsigned* pL0 = (const unsigned*)(sAlo + rA * KP + kO);
            const unsigned* pL8 = (const unsigned*)(sAlo + (rA + 8) * KP + kO);
            ahi[mt][0] = pH0[0]; ahi[mt][1] = pH8[0]; ahi[mt][2] = pH0[4]; ahi[mt][3] = pH8[4];
            alo[mt][0] = pL0[0]; alo[mt][1] = pL8[0]; alo[mt][2] = pL0[4]; alo[mt][3] = pL8[4];
        }
        #pragma unroll
        for (int n = 0; n < 8; n++) {
            int rB = n * 8 + g;
            const unsigned* qH = (const unsigned*)(sWhi + rB * KP + kO);
            const unsigned* qL = (const unsigned*)(sWlo + rB * KP + kO);
            unsigned bh0 = qH[0], bh1 = qH[4];
            unsigned bl0 = qL[0], bl1 = qL[4];
            #pragma unroll
            for (int mt = 0; mt < 2; mt++) {
                mma_bf16(acc[mt][n], ahi[mt], bh0, bh1);
                mma_bf16(acc[mt][n], ahi[mt], bl0, bl1);
                mma_bf16(acc[mt][n], alo[mt], bh0, bh1);
            }
        }
    }

    // epilogue: scale by dinv[row], write fp16
    __half2* C2 = (__half2*)C;
    #pragma unroll
    for (int mt = 0; mt < 2; mt++) {
        int r = r0 + wrow + mt * 16 + g;
        int r8 = r + 8;
        float dv  = (r  < N_NODES) ? g_dinv[r]  : 0.f;
        float dv8 = (r8 < N_NODES) ? g_dinv[r8] : 0.f;
        #pragma unroll
        for (int n = 0; n < 8; n++) {
            if (r < N_NODES)
                C2[(size_t)r * 32 + n * 4 + (t2 >> 1)] =
                    __floats2half2_rn(acc[mt][n][0] * dv, acc[mt][n][1] * dv);
            if (r8 < N_NODES)
                C2[(size_t)r8 * 32 + n * 4 + (t2 >> 1)] =
                    __floats2half2_rn(acc[mt][n][2] * dv8, acc[mt][n][3] * dv8);
        }
    }
}

// ---------------- CSR aggregation (fp16 gather, fp32 accumulate) ---------------
__device__ __forceinline__ void acc_row(float* a, uint4 r) {
    const __half2* p = (const __half2*)&r;
    #pragma unroll
    for (int i = 0; i < 4; i++) {
        float2 f = __half22float2(p[i]);
        a[2 * i] += f.x; a[2 * i + 1] += f.y;
    }
}

__global__ void k_aggregate() {
    int idx = blockIdx.x * blockDim.x + threadIdx.x;   // over N*8
    if (idx >= N_NODES * 8) return;
    int node = idx >> 3;
    int q = idx & 7;
    const uint4* h4 = (const uint4*)g_hH;

    float a[8], b[8];
    #pragma unroll
    for (int i = 0; i < 8; i++) { a[i] = 0.f; b[i] = 0.f; }
    acc_row(a, h4[(size_t)node * 8 + q]);   // self

    int e = g_rowoff[node], e1 = g_rowoff[node + 1];
    for (; e + 2 <= e1; e += 2) {
        int s0 = __ldg(&g_csr[e]);
        int s1 = __ldg(&g_csr[e + 1]);
        uint4 r0 = h4[(size_t)s0 * 8 + q];
        uint4 r1 = h4[(size_t)s1 * 8 + q];
        acc_row(a, r0);
        acc_row(b, r1);
    }
    if (e < e1) {
        int s0 = __ldg(&g_csr[e]);
        acc_row(a, h4[(size_t)s0 * 8 + q]);
    }

    float dv = g_dinv[node];
    #pragma unroll
    for (int i = 0; i < 8; i++) a[i] = (a[i] + b[i]) * dv;
    float4* agg4 = (float4*)g_agg;
    agg4[(size_t)node * 16 + q * 2]     = make_float4(a[0], a[1], a[2], a[3]);
    agg4[(size_t)node * 16 + q * 2 + 1] = make_float4(a[4], a[5], a[6], a[7]);
}

// ---------------- attention + pooling + final linear ---------------------------
__global__ void k_attn(const float* __restrict__ Wa, const float* __restrict__ v,
                       const float* __restrict__ Wl, const float* __restrict__ bl,
                       const float* __restrict__ b3,
                       float* __restrict__ out, float* __restrict__ lw) {
    __shared__ float sWaT[64 * 68];
    __shared__ float sWl[128 * 32];
    __shared__ float sV[64];
    __shared__ float sBl[32];
    __shared__ float sB3[64];
    __shared__ float sH[8][LEADS * 64];
    __shared__ float sScore[8][LEADS];
    __shared__ float sPool[8][128];

    int tid = threadIdx.x;
    for (int i = tid; i < 4096; i += 256) {
        int k = i >> 6, c = i & 63;
        sWaT[c * 68 + k] = Wa[i];
        sWl[i] = Wl[i];
    }
    if (tid < 64) { sV[tid] = v[tid]; sB3[tid] = b3[tid]; }
    if (tid < 32) sBl[tid] = bl[tid];
    __syncthreads();

    int w = tid >> 5, lane = tid & 31;
    int g = blockIdx.x * 8 + w;
    if (g >= NUM_GRAPHS) return;

    float* hs = sH[w];
    const float4* hg4 = (const float4*)(g_agg + (size_t)g * (LEADS * 64));
    const float4* b34 = (const float4*)sB3;
    float4* hs4 = (float4*)hs;
    #pragma unroll
    for (int j = 0; j < 6; j++) {
        int id = lane + 32 * j;
        float4 hv = hg4[id];
        float4 b = b34[id & 15];
        hv.x = fmaxf(hv.x + b.x, 0.f);
        hv.y = fmaxf(hv.y + b.y, 0.f);
        hv.z = fmaxf(hv.z + b.z, 0.f);
        hv.w = fmaxf(hv.w + b.w, 0.f);
        hs4[id] = hv;
    }
    __syncwarp();

    unsigned long long e0a[LEADS], e1a[LEADS];
    #pragma unroll
    for (int l = 0; l < LEADS; l++) { e0a[l] = 0ULL; e1a[l] = 0ULL; }
    const float* w0base = sWaT + lane * 68;
    const float* w1base = sWaT + (lane + 32) * 68;
    #pragma unroll 4
    for (int k4 = 0; k4 < 16; k4++) {
        ulonglong2 w0 = *(const ulonglong2*)(w0base + k4 * 4);
        ulonglong2 w1 = *(const ulonglong2*)(w1base + k4 * 4);
        #pragma unroll
        for (int l = 0; l < LEADS; l++) {
            ulonglong2 a = *(const ulonglong2*)(hs + l * 64 + k4 * 4);
            fma2(e0a[l], a.x, w0.x); fma2(e0a[l], a.y, w0.y);
            fma2(e1a[l], a.x, w1.x); fma2(e1a[l], a.y, w1.y);
        }
    }
    float v0 = sV[lane], v1 = sV[lane + 32];
    #pragma unroll
    for (int l = 0; l < LEADS; l++) {
        float s = tanhf(hsum2(e0a[l])) * v0 + tanhf(hsum2(e1a[l])) * v1;
        #pragma unroll
        for (int o = 16; o > 0; o >>= 1) s += __shfl_xor_sync(0xffffffff, s, o);
        if (lane == 0) sScore[w][l] = s;
    }
    __syncwarp();

    float sc[LEADS];
    #pragma unroll
    for (int l = 0; l < LEADS; l++) sc[l] = sScore[w][l];
    float m = sc[0];
    #pragma unroll
    for (int l = 1; l < LEADS; l++) m = fmaxf(m, sc[l]);
    float sum = 0.f;
    #pragma unroll
    for (int l = 0; l < LEADS; l++) { sc[l] = expf(sc[l] - m); sum += sc[l]; }
    float inv = 1.f / sum;
    #pragma unroll
    for (int l = 0; l < LEADS; l++) sc[l] *= inv;
    if (lane < LEADS) lw[(size_t)g * LEADS + lane] = sc[lane];

    #pragma unroll
    for (int half = 0; half < 2; half++) {
        int f = lane + 32 * half;
        float mx = -1e30f, sm = 0.f;
        #pragma unroll
        for (int l = 0; l < LEADS; l++) {
            float val = hs[l * 64 + f] * sc[l];
            mx = fmaxf(mx, val);
            sm += val;
        }
        sPool[w][f] = mx;
        sPool[w][64 + f] = sm * (1.f / 12.f);
    }
    __syncwarp();

    float acc = sBl[lane];
    #pragma unroll 16
    for (int f = 0; f < 128; f++) acc += sPool[w][f] * sWl[f * 32 + lane];
    out[(size_t)g * 32 + lane] = fmaxf(acc, 0.f);
}

// ---------------- launch --------------------------------------------------------
extern "C" void kernel_launch(void* const* d_in, const int* in_sizes, int n_in,
                              void* d_out, int out_size) {
    const float* x    = (const float*)d_in[0];
    const int*   ei   = (const int*)d_in[1];
    const int*   srcp = ei;
    const int*   dstp = ei + N_EDGES;
    const float* W1 = (const float*)d_in[3];
    const float* b1 = (const float*)d_in[4];
    const float* W2 = (const float*)d_in[5];
    const float* b2 = (const float*)d_in[6];
    const float* W3 = (const float*)d_in[7];
    const float* b3 = (const float*)d_in[8];
    const float* Wa = (const float*)d_in[9];
    const float* vv = (const float*)d_in[10];
    const float* Wl = (const float*)d_in[11];
    const float* bl = (const float*)d_in[12];

    float* out = (float*)d_out;                                  // [G,32]
    float* lw  = (float*)d_out + (size_t)NUM_GRAPHS * OUT_DIM;   // [G,12]

    __half* hp;  cudaGetSymbolAddress((void**)&hp,  g_hH);
    float* aggp; cudaGetSymbolAddress((void**)&aggp, g_agg);

    // smem: (2*BM + 2*64) * KP * 2 bytes
    const int SM1 = (2 * 128 + 2 * 64) * (128 + 8) * 2;   // 104448 B
    const int SM2 = (2 * 128 + 2 * 64) * (64 + 8) * 2;    //  55296 B
    cudaFuncSetAttribute(k_gemm_mma<128, false>, cudaFuncAttributeMaxDynamicSharedMemorySize, SM1);
    cudaFuncSetAttribute(k_gemm_mma<64, true>,  cudaFuncAttributeMaxDynamicSharedMemorySize, SM2);

    const int T = 256;
    const int gN = (N_NODES + T - 1) / T;
    const int gE = (N_EDGES + T - 1) / T;
    const int GRID = (N_NODES + 127) / 128;
    const int AGG_GRID = (N_NODES * 8 + T - 1) / T;

    // launches 1-3
    k_deg_zero<<<gN, T>>>();
    k_deg_count<<<gE, T>>>(dstp);
    k_dinv<<<gN, T>>>();

    // launch 4 (ncu-profiled slot): tensor-core layer-1 GEMM
    k_gemm_mma<128, false><<<GRID, 128, SM1>>>(x, W1, nullptr, hp);

    // CSR build
    k_scan1<<<SCAN_NB, 1024>>>();
    k_scan2<<<1, 1024>>>();
    k_scan3<<<(N_NODES + 1023) / 1024, 1024>>>();
    k_place<<<gE, T>>>(srcp, dstp);

    k_aggregate<<<AGG_GRID, T>>>();
    k_gemm_mma<64, true><<<GRID, 128, SM2>>>(aggp, W2, b1, hp);
    k_aggregate<<<AGG_GRID, T>>>();
    k_gemm_mma<64, true><<<GRID, 128, SM2>>>(aggp, W3, b2, hp);
    k_aggregate<<<AGG_GRID, T>>>();

    k_attn<<<(NUM_GRAPHS + 7) / 8, 256>>>(Wa, vv, Wl, bl, b3, out, lw);
}

// round 8
// speedup vs baseline: 1.7038x; 1.0615x over previous
#include <cuda_runtime.h>
#include <cuda_fp16.h>
#include <cuda_bf16.h>

#define N_NODES 600000
#define N_EDGES 2400000
#define LEADS 12
#define NUM_GRAPHS 50000
#define F_IN 128
#define HDIM 64
#define OUT_DIM 32

#define SCAN_NB 586   // ceil(600000/1024)

// ---------------- packed fp32x2 FMA (used in attention) ------------------------
__device__ __forceinline__ void fma2(unsigned long long& d,
                                     unsigned long long a,
                                     unsigned long long b) {
    asm("fma.rn.f32x2 %0, %1, %2, %0;" : "+l"(d) : "l"(a), "l"(b));
}
__device__ __forceinline__ float hsum2(unsigned long long d) {
    float lo = __uint_as_float((unsigned int)(d & 0xffffffffULL));
    float hi = __uint_as_float((unsigned int)(d >> 32));
    return lo + hi;
}

// ---------------- bf16 mma m16n8k16, fp32 accumulate ---------------------------
__device__ __forceinline__ void mma_bf16(float* c, const unsigned* a,
                                         unsigned b0, unsigned b1) {
    asm volatile(
        "mma.sync.aligned.m16n8k16.row.col.f32.bf16.bf16.f32 "
        "{%0,%1,%2,%3}, {%4,%5,%6,%7}, {%8,%9}, {%0,%1,%2,%3};"
        : "+f"(c[0]), "+f"(c[1]), "+f"(c[2]), "+f"(c[3])
        : "r"(a[0]), "r"(a[1]), "r"(a[2]), "r"(a[3]), "r"(b0), "r"(b1));
}

// ---------------- scratch (device globals) ------------------------------------
__device__ __half g_hH  [(size_t)N_NODES * HDIM];  // GEMM output (gather source)
__device__ __half g_aggH[(size_t)N_NODES * HDIM];  // aggregated layer output
__device__ float  g_dinv[N_NODES];
__device__ int    g_deg[N_NODES];
__device__ int    g_rowoff[N_NODES + 1];
__device__ int    g_cursor[N_NODES];
__device__ int    g_csr[N_EDGES];
__device__ int    g_bsum[SCAN_NB];
__device__ int    g_boff[SCAN_NB];

// ---------------- degree / CSR build -------------------------------------------
__global__ void k_deg_zero() {
    int i = blockIdx.x * blockDim.x + threadIdx.x;
    if (i < N_NODES) g_deg[i] = 0;
}

__global__ void k_deg_count(const int* __restrict__ dst) {
    int e = blockIdx.x * blockDim.x + threadIdx.x;
    if (e < N_EDGES) atomicAdd(&g_deg[dst[e]], 1);
}

__global__ void k_dinv() {
    int i = blockIdx.x * blockDim.x + threadIdx.x;
    if (i < N_NODES) g_dinv[i] = rsqrtf((float)(g_deg[i] + 1));
}

__global__ void k_scan1() {
    __shared__ int sh[1024];
    int i = blockIdx.x * 1024 + threadIdx.x;
    int v = (i < N_NODES) ? g_deg[i] : 0;
    sh[threadIdx.x] = v;
    __syncthreads();
    #pragma unroll
    for (int off = 1; off < 1024; off <<= 1) {
        int t = 0;
        if (threadIdx.x >= off) t = sh[threadIdx.x - off];
        __syncthreads();
        if (threadIdx.x >= off) sh[threadIdx.x] += t;
        __syncthreads();
    }
    if (i < N_NODES) g_rowoff[i] = sh[threadIdx.x] - v;   // exclusive
    if (threadIdx.x == 1023) g_bsum[blockIdx.x] = sh[1023];
}

__global__ void k_scan2() {
    __shared__ int sh[1024];
    int v = (threadIdx.x < SCAN_NB) ? g_bsum[threadIdx.x] : 0;
    sh[threadIdx.x] = v;
    __syncthreads();
    #pragma unroll
    for (int off = 1; off < 1024; off <<= 1) {
        int t = 0;
        if (threadIdx.x >= off) t = sh[threadIdx.x - off];
        __syncthreads();
        if (threadIdx.x >= off) sh[threadIdx.x] += t;
        __syncthreads();
    }
    if (threadIdx.x < SCAN_NB) g_boff[threadIdx.x] = sh[threadIdx.x] - v;
}

__global__ void k_scan3() {
    int i = blockIdx.x * blockDim.x + threadIdx.x;
    if (i < N_NODES) {
        int ro = g_rowoff[i] + g_boff[i >> 10];
        g_rowoff[i] = ro;
        g_cursor[i] = ro;
    }
    if (i == 0) g_rowoff[N_NODES] = N_EDGES;
}

__global__ void k_place(const int* __restrict__ src, const int* __restrict__ dst) {
    int e = blockIdx.x * blockDim.x + threadIdx.x;
    if (e < N_EDGES) {
        int pos = atomicAdd(&g_cursor[dst[e]], 1);
        g_csr[pos] = src[e];
    }
}

// ---------------- tensor-core GEMM: C_fp16 = (act(A) @ W) * dinv[row] ----------
// bf16 split (hi+lo), 3 HMMA products, fp32 accumulate. 256 threads, BM=128.
// Warp owns 16 rows (1 m-tile) x 64 cols (8 n-tiles). A input fp32 or fp16.
template<int K, bool ACT, bool HALF_IN>
__global__ void k_gemm_mma(const void* __restrict__ Ain, const float* __restrict__ W,
                           const float* __restrict__ bias, __half* __restrict__ C) {
    constexpr int BM = 128;
    constexpr int KP = K + 8;    // padded row
    constexpr int KQ = K / 4;
    extern __shared__ char smem_raw[];
    __nv_bfloat16* sAhi = (__nv_bfloat16*)smem_raw;            // [BM][KP]
    __nv_bfloat16* sAlo = sAhi + BM * KP;                      // [BM][KP]
    __nv_bfloat16* sWhi = sAlo + BM * KP;                      // [64][KP] (transposed)
    __nv_bfloat16* sWlo = sWhi + 64 * KP;                      // [64][KP]

    const int tid = threadIdx.x;
    const int r0 = blockIdx.x * BM;

    // stage W transposed, split hi/lo
    for (int i = tid; i < K * 64; i += 256) {
        int k = i >> 6, c = i & 63;
        float w = W[i];
        __nv_bfloat16 hi = __float2bfloat16_rn(w);
        sWhi[c * KP + k] = hi;
        sWlo[c * KP + k] = __float2bfloat16_rn(w - __bfloat162float(hi));
    }
    // stage A split hi/lo (+ optional fused bias+relu)
    const float4* B4 = (const float4*)bias;
    for (int i = tid; i < BM * KQ; i += 256) {
        int row = i / KQ, kq = i - row * KQ;
        float av[4] = {0.f, 0.f, 0.f, 0.f};
        if (r0 + row < N_NODES) {
            if (HALF_IN) {
                uint2 u = ((const uint2*)Ain)[(size_t)(r0 + row) * KQ + kq];
                float2 f0 = __half22float2(*(const __half2*)&u.x);
                float2 f1 = __half22float2(*(const __half2*)&u.y);
                av[0] = f0.x; av[1] = f0.y; av[2] = f1.x; av[3] = f1.y;
            } else {
                float4 a = ((const float4*)Ain)[(size_t)(r0 + row) * KQ + kq];
                av[0] = a.x; av[1] = a.y; av[2] = a.z; av[3] = a.w;
            }
        }
        if (ACT) {
            float4 b = B4[kq];
            av[0] = fmaxf(av[0] + b.x, 0.f);
            av[1] = fmaxf(av[1] + b.y, 0.f);
            av[2] = fmaxf(av[2] + b.z, 0.f);
            av[3] = fmaxf(av[3] + b.w, 0.f);
        }
        __nv_bfloat16 hv[4], lv[4];
        #pragma unroll
        for (int j = 0; j < 4; j++) {
            hv[j] = __float2bfloat16_rn(av[j]);
            lv[j] = __float2bfloat16_rn(av[j] - __bfloat162float(hv[j]));
        }
        __nv_bfloat162* ph = (__nv_bfloat162*)(sAhi + row * KP + kq * 4);
        __nv_bfloat162* pl = (__nv_bfloat162*)(sAlo + row * KP + kq * 4);
        ph[0] = __nv_bfloat162(hv[0], hv[1]);
        ph[1] = __nv_bfloat162(hv[2], hv[3]);
        pl[0] = __nv_bfloat162(lv[0], lv[1]);
        pl[1] = __nv_bfloat162(lv[2], lv[3]);
    }
    __syncthreads();

    const int warp = tid >> 5;
    const int lane = tid & 31;
    const int g  = lane >> 2;       // fragment group row / B col
    const int t2 = (lane & 3) * 2;  // fragment k-pair base
    const int wrow = warp * 16;     // warp's first row in block

    float acc[8][4];
    #pragma unroll
    for (int n = 0; n < 8; n++)
        #pragma unroll
        for (int c = 0; c < 4; c++) acc[n][c] = 0.f;

    #pragma unroll
    for (int kb = 0; kb < K / 16; kb++) {
        const int kO = kb * 16 + t2;
        unsigned ahi[4], alo[4];
        {
            int rA = wrow + g;
            const unsigned* pH0 = (const unsigned*)(sAhi + rA * KP + kO);
            const unsigned* pH8 = (const unsigned*)(sAhi + (rA + 8) * KP + kO);
            const unsigned* pL0 = (const unsigned*)(sAlo + rA * KP + kO);
            const unsigned* pL8 = (const unsigned*)(sAlo + (rA + 8) * KP + kO);
            ahi[0] = pH0[0]; ahi[1] = pH8[0]; ahi[2] = pH0[4]; ahi[3] = pH8[4];
            alo[0] = pL0[0]; alo[1] = pL8[0]; alo[2] = pL0[4]; alo[3] = pL8[4];
        }
        #pragma unroll
        for (int n = 0; n < 8; n++) {
            int rB = n * 8 + g;
            const unsigned* qH = (const unsigned*)(sWhi + rB * KP + kO);
            const unsigned* qL = (const unsigned*)(sWlo + rB * KP + kO);
            unsigned bh0 = qH[0], bh1 = qH[4];
            unsigned bl0 = qL[0], bl1 = qL[4];
            mma_bf16(acc[n], ahi, bh0, bh1);
            mma_bf16(acc[n], ahi, bl0, bl1);
            mma_bf16(acc[n], alo, bh0, bh1);
        }
    }

    // epilogue: scale by dinv[row], write fp16
    __half2* C2 = (__half2*)C;
    int r  = r0 + wrow + g;
    int r8 = r + 8;
    float dv  = (r  < N_NODES) ? g_dinv[r]  : 0.f;
    float dv8 = (r8 < N_NODES) ? g_dinv[r8] : 0.f;
    #pragma unroll
    for (int n = 0; n < 8; n++) {
        if (r < N_NODES)
            C2[(size_t)r * 32 + n * 4 + (t2 >> 1)] =
                __floats2half2_rn(acc[n][0] * dv, acc[n][1] * dv);
        if (r8 < N_NODES)
            C2[(size_t)r8 * 32 + n * 4 + (t2 >> 1)] =
                __floats2half2_rn(acc[n][2] * dv8, acc[n][3] * dv8);
    }
}

// ---------------- CSR aggregation (fp16 gather, fp32 accumulate, fp16 out) -----
__device__ __forceinline__ void acc_row(float* a, uint4 r) {
    const __half2* p = (const __half2*)&r;
    #pragma unroll
    for (int i = 0; i < 4; i++) {
        float2 f = __half22float2(p[i]);
        a[2 * i] += f.x; a[2 * i + 1] += f.y;
    }
}

__global__ void k_aggregate() {
    int idx = blockIdx.x * blockDim.x + threadIdx.x;   // over N*8
    if (idx >= N_NODES * 8) return;
    int node = idx >> 3;
    int q = idx & 7;
    const uint4* h4 = (const uint4*)g_hH;

    float a[8], b[8];
    #pragma unroll
    for (int i = 0; i < 8; i++) { a[i] = 0.f; b[i] = 0.f; }
    acc_row(a, h4[(size_t)node * 8 + q]);   // self

    int e = g_rowoff[node], e1 = g_rowoff[node + 1];
    for (; e + 2 <= e1; e += 2) {
        int s0 = __ldg(&g_csr[e]);
        int s1 = __ldg(&g_csr[e + 1]);
        uint4 r0 = h4[(size_t)s0 * 8 + q];
        uint4 r1 = h4[(size_t)s1 * 8 + q];
        acc_row(a, r0);
        acc_row(b, r1);
    }
    if (e < e1) {
        int s0 = __ldg(&g_csr[e]);
        acc_row(a, h4[(size_t)s0 * 8 + q]);
    }

    float dv = g_dinv[node];
    uint4 o;
    __half2* po = (__half2*)&o;
    #pragma unroll
    for (int i = 0; i < 4; i++)
        po[i] = __floats2half2_rn((a[2 * i] + b[2 * i]) * dv,
                                  (a[2 * i + 1] + b[2 * i + 1]) * dv);
    ((uint4*)g_aggH)[idx] = o;
}

// ---------------- attention + pooling + final linear ---------------------------
__global__ void k_attn(const float* __restrict__ Wa, const float* __restrict__ v,
                       const float* __restrict__ Wl, const float* __restrict__ bl,
                       const float* __restrict__ b3,
                       float* __restrict__ out, float* __restrict__ lw) {
    __shared__ float sWaT[64 * 68];
    __shared__ float sWl[128 * 32];
    __shared__ float sV[64];
    __shared__ float sBl[32];
    __shared__ float sB3[64];
    __shared__ float sH[8][LEADS * 64];
    __shared__ float sScore[8][LEADS];
    __shared__ float sPool[8][128];

    int tid = threadIdx.x;
    for (int i = tid; i < 4096; i += 256) {
        int k = i >> 6, c = i & 63;
        sWaT[c * 68 + k] = Wa[i];
        sWl[i] = Wl[i];
    }
    if (tid < 64) { sV[tid] = v[tid]; sB3[tid] = b3[tid]; }
    if (tid < 32) sBl[tid] = bl[tid];
    __syncthreads();

    int w = tid >> 5, lane = tid & 31;
    int g = blockIdx.x * 8 + w;
    if (g >= NUM_GRAPHS) return;

    float* hs = sH[w];
    const uint4* hg = (const uint4*)(g_aggH + (size_t)g * (LEADS * 64));  // 96 uint4
    #pragma unroll
    for (int j = 0; j < 3; j++) {
        int id = lane + 32 * j;      // 0..95
        uint4 u = hg[id];
        int lead = id >> 3;
        int fb = (id & 7) * 8;
        const __half2* p = (const __half2*)&u;
        #pragma unroll
        for (int i = 0; i < 4; i++) {
            float2 f = __half22float2(p[i]);
            hs[lead * 64 + fb + 2 * i]     = fmaxf(f.x + sB3[fb + 2 * i], 0.f);
            hs[lead * 64 + fb + 2 * i + 1] = fmaxf(f.y + sB3[fb + 2 * i + 1], 0.f);
        }
    }
    __syncwarp();

    unsigned long long e0a[LEADS], e1a[LEADS];
    #pragma unroll
    for (int l = 0; l < LEADS; l++) { e0a[l] = 0ULL; e1a[l] = 0ULL; }
    const float* w0base = sWaT + lane * 68;
    const float* w1base = sWaT + (lane + 32) * 68;
    #pragma unroll 4
    for (int k4 = 0; k4 < 16; k4++) {
        ulonglong2 w0 = *(const ulonglong2*)(w0base + k4 * 4);
        ulonglong2 w1 = *(const ulonglong2*)(w1base + k4 * 4);
        #pragma unroll
        for (int l = 0; l < LEADS; l++) {
            ulonglong2 a = *(const ulonglong2*)(hs + l * 64 + k4 * 4);
            fma2(e0a[l], a.x, w0.x); fma2(e0a[l], a.y, w0.y);
            fma2(e1a[l], a.x, w1.x); fma2(e1a[l], a.y, w1.y);
        }
    }
    float v0 = sV[lane], v1 = sV[lane + 32];
    #pragma unroll
    for (int l = 0; l < LEADS; l++) {
        float s = tanhf(hsum2(e0a[l])) * v0 + tanhf(hsum2(e1a[l])) * v1;
        #pragma unroll
        for (int o = 16; o > 0; o >>= 1) s += __shfl_xor_sync(0xffffffff, s, o);
        if (lane == 0) sScore[w][l] = s;
    }
    __syncwarp();

    float sc[LEADS];
    #pragma unroll
    for (int l = 0; l < LEADS; l++) sc[l] = sScore[w][l];
    float m = sc[0];
    #pragma unroll
    for (int l = 1; l < LEADS; l++) m = fmaxf(m, sc[l]);
    float sum = 0.f;
    #pragma unroll
    for (int l = 0; l < LEADS; l++) { sc[l] = expf(sc[l] - m); sum += sc[l]; }
    float inv = 1.f / sum;
    #pragma unroll
    for (int l = 0; l < LEADS; l++) sc[l] *= inv;
    if (lane < LEADS) lw[(size_t)g * LEADS + lane] = sc[lane];

    #pragma unroll
    for (int half = 0; half < 2; half++) {
        int f = lane + 32 * half;
        float mx = -1e30f, sm = 0.f;
        #pragma unroll
        for (int l = 0; l < LEADS; l++) {
            float val = hs[l * 64 + f] * sc[l];
            mx = fmaxf(mx, val);
            sm += val;
        }
        sPool[w][f] = mx;
        sPool[w][64 + f] = sm * (1.f / 12.f);
    }
    __syncwarp();

    float acc = sBl[lane];
    #pragma unroll 16
    for (int f = 0; f < 128; f++) acc += sPool[w][f] * sWl[f * 32 + lane];
    out[(size_t)g * 32 + lane] = fmaxf(acc, 0.f);
}

// ---------------- launch --------------------------------------------------------
extern "C" void kernel_launch(void* const* d_in, const int* in_sizes, int n_in,
                              void* d_out, int out_size) {
    const float* x    = (const float*)d_in[0];
    const int*   ei   = (const int*)d_in[1];
    const int*   srcp = ei;
    const int*   dstp = ei + N_EDGES;
    const float* W1 = (const float*)d_in[3];
    const float* b1 = (const float*)d_in[4];
    const float* W2 = (const float*)d_in[5];
    const float* b2 = (const float*)d_in[6];
    const float* W3 = (const float*)d_in[7];
    const float* b3 = (const float*)d_in[8];
    const float* Wa = (const float*)d_in[9];
    const float* vv = (const float*)d_in[10];
    const float* Wl = (const float*)d_in[11];
    const float* bl = (const float*)d_in[12];

    float* out = (float*)d_out;                                  // [G,32]
    float* lw  = (float*)d_out + (size_t)NUM_GRAPHS * OUT_DIM;   // [G,12]

    __half* hp;  cudaGetSymbolAddress((void**)&hp,  g_hH);
    __half* ap;  cudaGetSymbolAddress((void**)&ap,  g_aggH);

    const int SM1 = (2 * 128 + 2 * 64) * (128 + 8) * 2;   // 104448 B
    const int SM2 = (2 * 128 + 2 * 64) * (64 + 8) * 2;    //  55296 B
    cudaFuncSetAttribute(k_gemm_mma<128, false, false>, cudaFuncAttributeMaxDynamicSharedMemorySize, SM1);
    cudaFuncSetAttribute(k_gemm_mma<64, true, true>,   cudaFuncAttributeMaxDynamicSharedMemorySize, SM2);

    const int T = 256;
    const int gN = (N_NODES + T - 1) / T;
    const int gE = (N_EDGES + T - 1) / T;
    const int GRID = (N_NODES + 127) / 128;
    const int AGG_GRID = (N_NODES * 8 + T - 1) / T;

    // launches 1-3
    k_deg_zero<<<gN, T>>>();
    k_deg_count<<<gE, T>>>(dstp);
    k_dinv<<<gN, T>>>();

    // launch 4 (ncu-profiled slot): tensor-core layer-1 GEMM
    k_gemm_mma<128, false, false><<<GRID, 256, SM1>>>(x, W1, nullptr, hp);

    // CSR build
    k_scan1<<<SCAN_NB, 1024>>>();
    k_scan2<<<1, 1024>>>();
    k_scan3<<<(N_NODES + 1023) / 1024, 1024>>>();
    k_place<<<gE, T>>>(srcp, dstp);

    k_aggregate<<<AGG_GRID, T>>>();
    k_gemm_mma<64, true, true><<<GRID, 256, SM2>>>(ap, W2, b1, hp);
    k_aggregate<<<AGG_GRID, T>>>();
    k_gemm_mma<64, true, true><<<GRID, 256, SM2>>>(ap, W3, b2, hp);
    k_aggregate<<<AGG_GRID, T>>>();

    k_attn<<<(NUM_GRAPHS + 7) / 8, 256>>>(Wa, vv, Wl, bl, b3, out, lw);
}

// round 9
// speedup vs baseline: 1.7607x; 1.0334x over previous
#include <cuda_runtime.h>
#include <cuda_fp16.h>
#include <cuda_bf16.h>

#define N_NODES 600000
#define N_EDGES 2400000
#define LEADS 12
#define NUM_GRAPHS 50000
#define F_IN 128
#define HDIM 64
#define OUT_DIM 32

#define SCAN_NB 586   // ceil(600000/1024)

// ---------------- packed fp32x2 FMA (used in attention) ------------------------
__device__ __forceinline__ void fma2(unsigned long long& d,
                                     unsigned long long a,
                                     unsigned long long b) {
    asm("fma.rn.f32x2 %0, %1, %2, %0;" : "+l"(d) : "l"(a), "l"(b));
}
__device__ __forceinline__ float hsum2(unsigned long long d) {
    float lo = __uint_as_float((unsigned int)(d & 0xffffffffULL));
    float hi = __uint_as_float((unsigned int)(d >> 32));
    return lo + hi;
}

// ---------------- bf16 mma m16n8k16, fp32 accumulate ---------------------------
__device__ __forceinline__ void mma_bf16(float* c, const unsigned* a,
                                         unsigned b0, unsigned b1) {
    asm volatile(
        "mma.sync.aligned.m16n8k16.row.col.f32.bf16.bf16.f32 "
        "{%0,%1,%2,%3}, {%4,%5,%6,%7}, {%8,%9}, {%0,%1,%2,%3};"
        : "+f"(c[0]), "+f"(c[1]), "+f"(c[2]), "+f"(c[3])
        : "r"(a[0]), "r"(a[1]), "r"(a[2]), "r"(a[3]), "r"(b0), "r"(b1));
}

// ---------------- scratch (device globals) ------------------------------------
__device__ __half g_hH  [(size_t)N_NODES * HDIM];  // GEMM output (gather source)
__device__ __half g_aggH[(size_t)N_NODES * HDIM];  // aggregated layer output
__device__ float  g_dinv[N_NODES];
__device__ int    g_deg[N_NODES];
__device__ int    g_rowoff[N_NODES + 1];
__device__ int    g_cursor[N_NODES];
__device__ int    g_csr[N_EDGES];
__device__ int    g_bsum[SCAN_NB];
__device__ int    g_boff[SCAN_NB];

// ---------------- degree / CSR build -------------------------------------------
__global__ void k_deg_zero() {
    int i = blockIdx.x * blockDim.x + threadIdx.x;
    if (i < N_NODES) g_deg[i] = 0;
}

__global__ void k_deg_count(const int* __restrict__ dst) {
    int e = blockIdx.x * blockDim.x + threadIdx.x;
    if (e < N_EDGES) atomicAdd(&g_deg[dst[e]], 1);
}

__global__ void k_dinv() {
    int i = blockIdx.x * blockDim.x + threadIdx.x;
    if (i < N_NODES) g_dinv[i] = rsqrtf((float)(g_deg[i] + 1));
}

__global__ void k_scan1() {
    __shared__ int sh[1024];
    int i = blockIdx.x * 1024 + threadIdx.x;
    int v = (i < N_NODES) ? g_deg[i] : 0;
    sh[threadIdx.x] = v;
    __syncthreads();
    #pragma unroll
    for (int off = 1; off < 1024; off <<= 1) {
        int t = 0;
        if (threadIdx.x >= off) t = sh[threadIdx.x - off];
        __syncthreads();
        if (threadIdx.x >= off) sh[threadIdx.x] += t;
        __syncthreads();
    }
    if (i < N_NODES) g_rowoff[i] = sh[threadIdx.x] - v;   // exclusive
    if (threadIdx.x == 1023) g_bsum[blockIdx.x] = sh[1023];
}

__global__ void k_scan2() {
    __shared__ int sh[1024];
    int v = (threadIdx.x < SCAN_NB) ? g_bsum[threadIdx.x] : 0;
    sh[threadIdx.x] = v;
    __syncthreads();
    #pragma unroll
    for (int off = 1; off < 1024; off <<= 1) {
        int t = 0;
        if (threadIdx.x >= off) t = sh[threadIdx.x - off];
        __syncthreads();
        if (threadIdx.x >= off) sh[threadIdx.x] += t;
        __syncthreads();
    }
    if (threadIdx.x < SCAN_NB) g_boff[threadIdx.x] = sh[threadIdx.x] - v;
}

__global__ void k_scan3() {
    int i = blockIdx.x * blockDim.x + threadIdx.x;
    if (i < N_NODES) {
        int ro = g_rowoff[i] + g_boff[i >> 10];
        g_rowoff[i] = ro;
        g_cursor[i] = ro;
    }
    if (i == 0) g_rowoff[N_NODES] = N_EDGES;
}

__global__ void k_place(const int* __restrict__ src, const int* __restrict__ dst) {
    int e = blockIdx.x * blockDim.x + threadIdx.x;
    if (e < N_EDGES) {
        int pos = atomicAdd(&g_cursor[dst[e]], 1);
        g_csr[pos] = src[e];
    }
}

// ---------------- tensor-core GEMM: C_fp16 = (act(A) @ W) * dinv[row] ----------
// bf16 split (hi+lo), 3 HMMA products, fp32 accumulate. 256 threads, BM=128.
// Staging loads are front-batched (8 vectors in flight) to hide DRAM latency.
template<int K, bool ACT, bool HALF_IN>
__global__ void k_gemm_mma(const void* __restrict__ Ain, const float* __restrict__ W,
                           const float* __restrict__ bias, __half* __restrict__ C) {
    constexpr int BM = 128;
    constexpr int KP = K + 8;    // padded row
    constexpr int KQ = K / 4;
    constexpr int NIT = BM * KQ / 256;   // staging iterations (16 for K=128, 8 for K=64)
    extern __shared__ char smem_raw[];
    __nv_bfloat16* sAhi = (__nv_bfloat16*)smem_raw;            // [BM][KP]
    __nv_bfloat16* sAlo = sAhi + BM * KP;                      // [BM][KP]
    __nv_bfloat16* sWhi = sAlo + BM * KP;                      // [64][KP] (transposed)
    __nv_bfloat16* sWlo = sWhi + 64 * KP;                      // [64][KP]

    const int tid = threadIdx.x;
    const int r0 = blockIdx.x * BM;

    // stage W transposed, split hi/lo
    for (int i = tid; i < K * 64; i += 256) {
        int k = i >> 6, c = i & 63;
        float w = W[i];
        __nv_bfloat16 hi = __float2bfloat16_rn(w);
        sWhi[c * KP + k] = hi;
        sWlo[c * KP + k] = __float2bfloat16_rn(w - __bfloat162float(hi));
    }

    // stage A split hi/lo (+ optional fused bias+relu), front-batched loads
    const float4* B4 = (const float4*)bias;
    #pragma unroll
    for (int base = 0; base < NIT; base += 8) {
        float av[8][4];
        // batch 8 guarded loads (8 outstanding LDGs per thread)
        #pragma unroll
        for (int j = 0; j < 8; j++) {
            int i = tid + (base + j) * 256;
            int row = i / KQ, kq = i - row * KQ;
            av[j][0] = 0.f; av[j][1] = 0.f; av[j][2] = 0.f; av[j][3] = 0.f;
            if (r0 + row < N_NODES) {
                if (HALF_IN) {
                    uint2 u = __ldg(((const uint2*)Ain) + (size_t)(r0 + row) * KQ + kq);
                    float2 f0 = __half22float2(*(const __half2*)&u.x);
                    float2 f1 = __half22float2(*(const __half2*)&u.y);
                    av[j][0] = f0.x; av[j][1] = f0.y; av[j][2] = f1.x; av[j][3] = f1.y;
                } else {
                    float4 a = __ldg(((const float4*)Ain) + (size_t)(r0 + row) * KQ + kq);
                    av[j][0] = a.x; av[j][1] = a.y; av[j][2] = a.z; av[j][3] = a.w;
                }
            }
        }
        // convert + store
        #pragma unroll
        for (int j = 0; j < 8; j++) {
            int i = tid + (base + j) * 256;
            int row = i / KQ, kq = i - row * KQ;
            if (ACT) {
                float4 b = B4[kq];
                av[j][0] = fmaxf(av[j][0] + b.x, 0.f);
                av[j][1] = fmaxf(av[j][1] + b.y, 0.f);
                av[j][2] = fmaxf(av[j][2] + b.z, 0.f);
                av[j][3] = fmaxf(av[j][3] + b.w, 0.f);
            }
            __nv_bfloat16 hv[4], lv[4];
            #pragma unroll
            for (int q = 0; q < 4; q++) {
                hv[q] = __float2bfloat16_rn(av[j][q]);
                lv[q] = __float2bfloat16_rn(av[j][q] - __bfloat162float(hv[q]));
            }
            __nv_bfloat162* ph = (__nv_bfloat162*)(sAhi + row * KP + kq * 4);
            __nv_bfloat162* pl = (__nv_bfloat162*)(sAlo + row * KP + kq * 4);
            ph[0] = __nv_bfloat162(hv[0], hv[1]);
            ph[1] = __nv_bfloat162(hv[2], hv[3]);
            pl[0] = __nv_bfloat162(lv[0], lv[1]);
            pl[1] = __nv_bfloat162(lv[2], lv[3]);
        }
    }
    __syncthreads();

    const int warp = tid >> 5;
    const int lane = tid & 31;
    const int g  = lane >> 2;       // fragment group row / B col
    const int t2 = (lane & 3) * 2;  // fragment k-pair base
    const int wrow = warp * 16;     // warp's first row in block

    float acc[8][4];
    #pragma unroll
    for (int n = 0; n < 8; n++)
        #pragma unroll
        for (int c = 0; c < 4; c++) acc[n][c] = 0.f;

    #pragma unroll
    for (int kb = 0; kb < K / 16; kb++) {
        const int kO = kb * 16 + t2;
        unsigned ahi[4], alo[4];
        {
            int rA = wrow + g;
            const unsigned* pH0 = (const unsigned*)(sAhi + rA * KP + kO);
            const unsigned* pH8 = (const unsigned*)(sAhi + (rA + 8) * KP + kO);
            const unsigned* pL0 = (const unsigned*)(sAlo + rA * KP + kO);
            const unsigned* pL8 = (const unsigned*)(sAlo + (rA + 8) * KP + kO);
            ahi[0] = pH0[0]; ahi[1] = pH8[0]; ahi[2] = pH0[4]; ahi[3] = pH8[4];
            alo[0] = pL0[0]; alo[1] = pL8[0]; alo[2] = pL0[4]; alo[3] = pL8[4];
        }
        #pragma unroll
        for (int n = 0; n < 8; n++) {
            int rB = n * 8 + g;
            const unsigned* qH = (const unsigned*)(sWhi + rB * KP + kO);
            const unsigned* qL = (const unsigned*)(sWlo + rB * KP + kO);
            unsigned bh0 = qH[0], bh1 = qH[4];
            unsigned bl0 = qL[0], bl1 = qL[4];
            mma_bf16(acc[n], ahi, bh0, bh1);
            mma_bf16(acc[n], ahi, bl0, bl1);
            mma_bf16(acc[n], alo, bh0, bh1);
        }
    }

    // epilogue: scale by dinv[row], write fp16
    __half2* C2 = (__half2*)C;
    int r  = r0 + wrow + g;
    int r8 = r + 8;
    float dv  = (r  < N_NODES) ? g_dinv[r]  : 0.f;
    float dv8 = (r8 < N_NODES) ? g_dinv[r8] : 0.f;
    #pragma unroll
    for (int n = 0; n < 8; n++) {
        if (r < N_NODES)
            C2[(size_t)r * 32 + n * 4 + (t2 >> 1)] =
                __floats2half2_rn(acc[n][0] * dv, acc[n][1] * dv);
        if (r8 < N_NODES)
            C2[(size_t)r8 * 32 + n * 4 + (t2 >> 1)] =
                __floats2half2_rn(acc[n][2] * dv8, acc[n][3] * dv8);
    }
}

// ---------------- CSR aggregation: one warp per node (divergence-free) ---------
// Lane owns one __half2 feature pair (32 lanes x 4B = full 128B row per gather).
__global__ void k_aggregate() {
    int gw = (blockIdx.x * blockDim.x + threadIdx.x) >> 5;
    if (gw >= N_NODES) return;
    const int lane = threadIdx.x & 31;
    const int node = gw;
    const __half2* h2 = (const __half2*)g_hH;   // row = 32 half2

    float2 a0 = __half22float2(h2[(size_t)node * 32 + lane]);   // self
    float2 a1 = make_float2(0.f, 0.f);

    int e  = g_rowoff[node];
    int e1 = g_rowoff[node + 1];
    for (; e + 2 <= e1; e += 2) {
        int s0 = __ldg(&g_csr[e]);
        int s1 = __ldg(&g_csr[e + 1]);
        float2 v0 = __half22float2(h2[(size_t)s0 * 32 + lane]);
        float2 v1 = __half22float2(h2[(size_t)s1 * 32 + lane]);
        a0.x += v0.x; a0.y += v0.y;
        a1.x += v1.x; a1.y += v1.y;
    }
    if (e < e1) {
        int s0 = __ldg(&g_csr[e]);
        float2 v0 = __half22float2(h2[(size_t)s0 * 32 + lane]);
        a0.x += v0.x; a0.y += v0.y;
    }

    float dv = g_dinv[node];
    ((__half2*)g_aggH)[(size_t)node * 32 + lane] =
        __floats2half2_rn((a0.x + a1.x) * dv, (a0.y + a1.y) * dv);
}

// ---------------- attention + pooling + final linear ---------------------------
__global__ void k_attn(const float* __restrict__ Wa, const float* __restrict__ v,
                       const float* __restrict__ Wl, const float* __restrict__ bl,
                       const float* __restrict__ b3,
                       float* __restrict__ out, float* __restrict__ lw) {
    __shared__ float sWaT[64 * 68];
    __shared__ float sWl[128 * 32];
    __shared__ float sV[64];
    __shared__ float sBl[32];
    __shared__ float sB3[64];
    __shared__ float sH[8][LEADS * 64];
    __shared__ float sScore[8][LEADS];
    __shared__ float sPool[8][128];

    int tid = threadIdx.x;
    for (int i = tid; i < 4096; i += 256) {
        int k = i >> 6, c = i & 63;
        sWaT[c * 68 + k] = Wa[i];
        sWl[i] = Wl[i];
    }
    if (tid < 64) { sV[tid] = v[tid]; sB3[tid] = b3[tid]; }
    if (tid < 32) sBl[tid] = bl[tid];
    __syncthreads();

    int w = tid >> 5, lane = tid & 31;
    int g = blockIdx.x * 8 + w;
    if (g >= NUM_GRAPHS) return;

    float* hs = sH[w];
    const uint4* hg = (const uint4*)(g_aggH + (size_t)g * (LEADS * 64));  // 96 uint4
    #pragma unroll
    for (int j = 0; j < 3; j++) {
        int id = lane + 32 * j;      // 0..95
        uint4 u = hg[id];
        int lead = id >> 3;
        int fb = (id & 7) * 8;
        const __half2* p = (const __half2*)&u;
        #pragma unroll
        for (int i = 0; i < 4; i++) {
            float2 f = __half22float2(p[i]);
            hs[lead * 64 + fb + 2 * i]     = fmaxf(f.x + sB3[fb + 2 * i], 0.f);
            hs[lead * 64 + fb + 2 * i + 1] = fmaxf(f.y + sB3[fb + 2 * i + 1], 0.f);
        }
    }
    __syncwarp();

    unsigned long long e0a[LEADS], e1a[LEADS];
    #pragma unroll
    for (int l = 0; l < LEADS; l++) { e0a[l] = 0ULL; e1a[l] = 0ULL; }
    const float* w0base = sWaT + lane * 68;
    const float* w1base = sWaT + (lane + 32) * 68;
    #pragma unroll 4
    for (int k4 = 0; k4 < 16; k4++) {
        ulonglong2 w0 = *(const ulonglong2*)(w0base + k4 * 4);
        ulonglong2 w1 = *(const ulonglong2*)(w1base + k4 * 4);
        #pragma unroll
        for (int l = 0; l < LEADS; l++) {
            ulonglong2 a = *(const ulonglong2*)(hs + l * 64 + k4 * 4);
            fma2(e0a[l], a.x, w0.x); fma2(e0a[l], a.y, w0.y);
            fma2(e1a[l], a.x, w1.x); fma2(e1a[l], a.y, w1.y);
        }
    }
    float v0 = sV[lane], v1 = sV[lane + 32];
    #pragma unroll
    for (int l = 0; l < LEADS; l++) {
        float s = tanhf(hsum2(e0a[l])) * v0 + tanhf(hsum2(e1a[l])) * v1;
        #pragma unroll
        for (int o = 16; o > 0; o >>= 1) s += __shfl_xor_sync(0xffffffff, s, o);
        if (lane == 0) sScore[w][l] = s;
    }
    __syncwarp();

    float sc[LEADS];
    #pragma unroll
    for (int l = 0; l < LEADS; l++) sc[l] = sScore[w][l];
    float m = sc[0];
    #pragma unroll
    for (int l = 1; l < LEADS; l++) m = fmaxf(m, sc[l]);
    float sum = 0.f;
    #pragma unroll
    for (int l = 0; l < LEADS; l++) { sc[l] = expf(sc[l] - m); sum += sc[l]; }
    float inv = 1.f / sum;
    #pragma unroll
    for (int l = 0; l < LEADS; l++) sc[l] *= inv;
    if (lane < LEADS) lw[(size_t)g * LEADS + lane] = sc[lane];

    #pragma unroll
    for (int half = 0; half < 2; half++) {
        int f = lane + 32 * half;
        float mx = -1e30f, sm = 0.f;
        #pragma unroll
        for (int l = 0; l < LEADS; l++) {
            float val = hs[l * 64 + f] * sc[l];
            mx = fmaxf(mx, val);
            sm += val;
        }
        sPool[w][f] = mx;
        sPool[w][64 + f] = sm * (1.f / 12.f);
    }
    __syncwarp();

    float acc = sBl[lane];
    #pragma unroll 16
    for (int f = 0; f < 128; f++) acc += sPool[w][f] * sWl[f * 32 + lane];
    out[(size_t)g * 32 + lane] = fmaxf(acc, 0.f);
}

// ---------------- launch --------------------------------------------------------
extern "C" void kernel_launch(void* const* d_in, const int* in_sizes, int n_in,
                              void* d_out, int out_size) {
    const float* x    = (const float*)d_in[0];
    const int*   ei   = (const int*)d_in[1];
    const int*   srcp = ei;
    const int*   dstp = ei + N_EDGES;
    const float* W1 = (const float*)d_in[3];
    const float* b1 = (const float*)d_in[4];
    const float* W2 = (const float*)d_in[5];
    const float* b2 = (const float*)d_in[6];
    const float* W3 = (const float*)d_in[7];
    const float* b3 = (const float*)d_in[8];
    const float* Wa = (const float*)d_in[9];
    const float* vv = (const float*)d_in[10];
    const float* Wl = (const float*)d_in[11];
    const float* bl = (const float*)d_in[12];

    float* out = (float*)d_out;                                  // [G,32]
    float* lw  = (float*)d_out + (size_t)NUM_GRAPHS * OUT_DIM;   // [G,12]

    __half* hp;  cudaGetSymbolAddress((void**)&hp,  g_hH);
    __half* ap;  cudaGetSymbolAddress((void**)&ap,  g_aggH);

    const int SM1 = (2 * 128 + 2 * 64) * (128 + 8) * 2;   // 104448 B
    const int SM2 = (2 * 128 + 2 * 64) * (64 + 8) * 2;    //  55296 B
    cudaFuncSetAttribute(k_gemm_mma<128, false, false>, cudaFuncAttributeMaxDynamicSharedMemorySize, SM1);
    cudaFuncSetAttribute(k_gemm_mma<64, true, true>,   cudaFuncAttributeMaxDynamicSharedMemorySize, SM2);

    const int T = 256;
    const int gN = (N_NODES + T - 1) / T;
    const int gE = (N_EDGES + T - 1) / T;
    const int GRID = (N_NODES + 127) / 128;
    const int AGG_GRID = (int)(((size_t)N_NODES * 32 + T - 1) / T);

    // launches 1-3
    k_deg_zero<<<gN, T>>>();
    k_deg_count<<<gE, T>>>(dstp);
    k_dinv<<<gN, T>>>();

    // launch 4 (ncu-profiled slot): tensor-core layer-1 GEMM
    k_gemm_mma<128, false, false><<<GRID, 256, SM1>>>(x, W1, nullptr, hp);

    // CSR build
    k_scan1<<<SCAN_NB, 1024>>>();
    k_scan2<<<1, 1024>>>();
    k_scan3<<<(N_NODES + 1023) / 1024, 1024>>>();
    k_place<<<gE, T>>>(srcp, dstp);

    k_aggregate<<<AGG_GRID, T>>>();
    k_gemm_mma<64, true, true><<<GRID, 256, SM2>>>(ap, W2, b1, hp);
    k_aggregate<<<AGG_GRID, T>>>();
    k_gemm_mma<64, true, true><<<GRID, 256, SM2>>>(ap, W3, b2, hp);
    k_aggregate<<<AGG_GRID, T>>>();

    k_attn<<<(NUM_GRAPHS + 7) / 8, 256>>>(Wa, vv, Wl, bl, b3, out, lw);
}